// round 2
// baseline (speedup 1.0000x reference)
#include <cuda_runtime.h>

#define S 1024
#define NB 4
#define PLANE (S * S)
#define TEXELS (NB * PLANE)   // 4M texels
#define EPS 1e-8f

// Scratch: 64 MB accumulator (rgb + weight) and 64 MB ping-pong buffer (rgb + mask).
__device__ float4 g_acc[TEXELS];
__device__ float4 g_buf[TEXELS];

// ---------------------------------------------------------------------------
// Zero the accumulator (graph is replayed; must re-zero every launch).
// ---------------------------------------------------------------------------
__global__ void zero_kernel() {
    int i = blockIdx.x * blockDim.x + threadIdx.x;
    g_acc[i] = make_float4(0.f, 0.f, 0.f, 0.f);
}

// Vectorized L2 reduction: one 16B atomic add instead of 4 scalar atomicAdds.
__device__ __forceinline__ void red_add_v4(float4* addr, float a, float b, float c, float d) {
    asm volatile("red.global.add.v4.f32 [%0], {%1, %2, %3, %4};"
                 :: "l"(addr), "f"(a), "f"(b), "f"(c), "f"(d)
                 : "memory");
}

// ---------------------------------------------------------------------------
// Bilinear splat: one thread per source pixel, 4 corner RED.v4 ops.
// All rounding-sensitive math uses explicit _rn intrinsics so nvcc cannot
// FMA-contract (reference rounds mul and sub separately; contraction of
// v = 1023 - y*1023 flips floor() for ~hundreds of pixels -> 1e-3 error).
// ---------------------------------------------------------------------------
__global__ void splat_kernel(const float* __restrict__ img,
                             const float2* __restrict__ uv) {
    int tid = blockIdx.x * blockDim.x + threadIdx.x;   // 0 .. 4M-1
    int n  = tid >> 20;
    int hw = tid & (PLANE - 1);

    float2 t = uv[tid];
    const float* base = img + (size_t)n * 3 * PLANE + hw;
    float r = __ldg(base);
    float g = __ldg(base + PLANE);
    float b = __ldg(base + 2 * PLANE);

    float u = __fmul_rn(t.x, 1023.0f);
    float v = __fsub_rn(1023.0f, __fmul_rn(t.y, 1023.0f));
    float x0f = floorf(u), y0f = floorf(v);
    float fx = __fsub_rn(u, x0f);
    float fy = __fsub_rn(v, y0f);
    int x0 = (int)x0f, y0 = (int)y0f;
    int x1 = x0 + 1,   y1 = y0 + 1;

    float gx = __fsub_rn(1.0f, fx);
    float gy = __fsub_rn(1.0f, fy);
    float w00 = __fmul_rn(gx, gy);
    float w10 = __fmul_rn(fx, gy);
    float w01 = __fmul_rn(gx, fy);
    float w11 = __fmul_rn(fx, fy);

    float4* accn = g_acc + n * PLANE;

    #define CORNER(XI, YI, WT) do {                                         \
        int xi = (XI), yi = (YI);                                           \
        float wt = (WT);                                                    \
        bool valid = ((unsigned)xi < (unsigned)S) &&                        \
                     ((unsigned)yi < (unsigned)S);                          \
        wt = valid ? wt : 0.f;                                              \
        int xc = min(max(xi, 0), S - 1);                                    \
        int yc = min(max(yi, 0), S - 1);                                    \
        red_add_v4(accn + yc * S + xc,                                      \
                   __fmul_rn(r, wt), __fmul_rn(g, wt),                      \
                   __fmul_rn(b, wt), wt);                                   \
    } while (0)

    CORNER(x0, y0, w00);
    CORNER(x1, y0, w10);
    CORNER(x0, y1, w01);
    CORNER(x1, y1, w11);
    #undef CORNER
}

// ---------------------------------------------------------------------------
// Hole-fill stencil. Invariant of the stored (p, m) pairs: p == tex * m
// (unfilled texels carry 0), so each iteration is the same stencil:
//   nsum = box3(p), ncnt = box3(m)
//   out_p = m_center ? p_center : (ncnt > 0 ? nsum/ncnt : 0)
//   out_m = m_center | (ncnt > 0)
// FIRST iteration normalizes the raw accumulator while loading into smem
// (fusing the normalize pass) and writes g_buf; the second reads g_buf and
// writes the final packed [N,S,S,3] output. Divisions are exact IEEE (_rn)
// to match the reference.
// ---------------------------------------------------------------------------
__device__ __forceinline__ float4 add3(float4 a, float4 b, float4 c) {
    return make_float4(__fadd_rn(__fadd_rn(a.x, b.x), c.x),
                       __fadd_rn(__fadd_rn(a.y, b.y), c.y),
                       __fadd_rn(__fadd_rn(a.z, b.z), c.z),
                       __fadd_rn(__fadd_rn(a.w, b.w), c.w));
}

template<bool FIRST>
__global__ void fill_kernel(float* __restrict__ otex) {
    __shared__ float4 sm[34][34];   // (p, m) tile + halo
    __shared__ float4 hs[34][32];   // horizontal 3-sums

    const float4* __restrict__ in = FIRST ? g_acc : g_buf;

    int n   = blockIdx.z;
    int tx0 = blockIdx.x << 5;
    int ty0 = blockIdx.y << 5;
    const float4* base = in + n * PLANE;
    int t = threadIdx.x;   // 256 threads

    // Load 34x34 halo region; zero outside the image (per-batch padding).
    for (int i = t; i < 34 * 34; i += 256) {
        int ly = i / 34, lx = i - ly * 34;
        int gx = tx0 + lx - 1, gy = ty0 + ly - 1;
        float4 v = make_float4(0.f, 0.f, 0.f, 0.f);
        if ((unsigned)gx < (unsigned)S && (unsigned)gy < (unsigned)S) {
            v = base[gy * S + gx];
            if (FIRST) {
                // normalize: tex = acc / max(w, eps); p = tex * m; m = w > 0
                float m  = v.w > 0.f ? 1.f : 0.f;
                float d  = fmaxf(v.w, EPS);
                v.x = __fmul_rn(__fdiv_rn(v.x, d), m);
                v.y = __fmul_rn(__fdiv_rn(v.y, d), m);
                v.z = __fmul_rn(__fdiv_rn(v.z, d), m);
                v.w = m;
            }
        }
        sm[ly][lx] = v;
    }
    __syncthreads();

    // Separable box: horizontal 3-sums (34 rows x 32 interior cols).
    for (int i = t; i < 34 * 32; i += 256) {
        int ly = i >> 5, lx = i & 31;
        hs[ly][lx] = add3(sm[ly][lx], sm[ly][lx + 1], sm[ly][lx + 2]);
    }
    __syncthreads();

    // Vertical 3-sums + finalize: 32x32 outputs, 8 rows of threads x 4 iters.
    int lx = t & 31;
    for (int ly = t >> 5; ly < 32; ly += 8) {
        float4 ns  = add3(hs[ly][lx], hs[ly + 1][lx], hs[ly + 2][lx]);
        float4 cen = sm[ly + 1][lx + 1];

        bool covered = cen.w > 0.f;
        float nm = ns.w > 0.f ? 1.f : 0.f;
        float nd = fmaxf(ns.w, EPS);

        float ox = covered ? cen.x : __fmul_rn(__fdiv_rn(ns.x, nd), nm);
        float oy = covered ? cen.y : __fmul_rn(__fdiv_rn(ns.y, nd), nm);
        float oz = covered ? cen.z : __fmul_rn(__fdiv_rn(ns.z, nd), nm);

        int gy = ty0 + ly, gx = tx0 + lx;
        if (FIRST) {
            float om = fmaxf(cen.w, nm);
            g_buf[n * PLANE + gy * S + gx] = make_float4(ox, oy, oz, om);
        } else {
            float* o = otex + ((size_t)n * PLANE + (size_t)gy * S + gx) * 3;
            o[0] = ox; o[1] = oy; o[2] = oz;
        }
    }
}

// ---------------------------------------------------------------------------
// Launch: zero -> splat -> fill1 (normalize fused) -> fill2 (-> d_out)
// ---------------------------------------------------------------------------
extern "C" void kernel_launch(void* const* d_in, const int* in_sizes, int n_in,
                              void* d_out, int out_size) {
    const float*  img = (const float*)d_in[0];      // [4,3,1024,1024]
    const float2* uv  = (const float2*)d_in[1];     // [4,1024,1024,2]
    float* out = (float*)d_out;                     // [4,1024,1024,3]

    zero_kernel<<<TEXELS / 256, 256>>>();
    splat_kernel<<<TEXELS / 256, 256>>>(img, uv);

    dim3 grid(S / 32, S / 32, NB);
    fill_kernel<true ><<<grid, 256>>>(out);
    fill_kernel<false><<<grid, 256>>>(out);
}

// round 3
// speedup vs baseline: 1.0919x; 1.0919x over previous
#include <cuda_runtime.h>

#define S 1024
#define NB 4
#define PLANE (S * S)
#define TEXELS (NB * PLANE)   // 4M texels
#define EPS 1e-8f

// Scratch: 64 MB accumulator (rgb + weight).
__device__ float4 g_acc[TEXELS];

// ---------------------------------------------------------------------------
// Zero the accumulator (graph is replayed; must re-zero every launch).
// ---------------------------------------------------------------------------
__global__ void zero_kernel() {
    int i = blockIdx.x * blockDim.x + threadIdx.x;
    g_acc[i] = make_float4(0.f, 0.f, 0.f, 0.f);
}

// Vectorized L2 reduction: one 16B atomic add instead of 4 scalar atomicAdds.
__device__ __forceinline__ void red_add_v4(float4* addr, float a, float b, float c, float d) {
    asm volatile("red.global.add.v4.f32 [%0], {%1, %2, %3, %4};"
                 :: "l"(addr), "f"(a), "f"(b), "f"(c), "f"(d)
                 : "memory");
}

// ---------------------------------------------------------------------------
// Bilinear splat: one thread per source pixel, 4 corner RED.v4 ops.
// All rounding-sensitive math uses explicit _rn intrinsics so nvcc cannot
// FMA-contract (reference rounds mul and sub separately; contraction of
// v = 1023 - y*1023 flips floor() for ~hundreds of pixels -> 1e-3 error).
// ---------------------------------------------------------------------------
__global__ void splat_kernel(const float* __restrict__ img,
                             const float2* __restrict__ uv) {
    int tid = blockIdx.x * blockDim.x + threadIdx.x;   // 0 .. 4M-1
    int n  = tid >> 20;
    int hw = tid & (PLANE - 1);

    float2 t = uv[tid];
    const float* base = img + (size_t)n * 3 * PLANE + hw;
    float r = __ldg(base);
    float g = __ldg(base + PLANE);
    float b = __ldg(base + 2 * PLANE);

    float u = __fmul_rn(t.x, 1023.0f);
    float v = __fsub_rn(1023.0f, __fmul_rn(t.y, 1023.0f));
    float x0f = floorf(u), y0f = floorf(v);
    float fx = __fsub_rn(u, x0f);
    float fy = __fsub_rn(v, y0f);
    int x0 = (int)x0f, y0 = (int)y0f;
    int x1 = x0 + 1,   y1 = y0 + 1;

    float gx = __fsub_rn(1.0f, fx);
    float gy = __fsub_rn(1.0f, fy);
    float w00 = __fmul_rn(gx, gy);
    float w10 = __fmul_rn(fx, gy);
    float w01 = __fmul_rn(gx, fy);
    float w11 = __fmul_rn(fx, fy);

    float4* accn = g_acc + n * PLANE;

    #define CORNER(XI, YI, WT) do {                                         \
        int xi = (XI), yi = (YI);                                           \
        float wt = (WT);                                                    \
        bool valid = ((unsigned)xi < (unsigned)S) &&                        \
                     ((unsigned)yi < (unsigned)S);                          \
        wt = valid ? wt : 0.f;                                              \
        int xc = min(max(xi, 0), S - 1);                                    \
        int yc = min(max(yi, 0), S - 1);                                    \
        red_add_v4(accn + yc * S + xc,                                      \
                   __fmul_rn(r, wt), __fmul_rn(g, wt),                      \
                   __fmul_rn(b, wt), wt);                                   \
    } while (0)

    CORNER(x0, y0, w00);
    CORNER(x1, y0, w10);
    CORNER(x0, y1, w01);
    CORNER(x1, y1, w11);
    #undef CORNER
}

// ---------------------------------------------------------------------------
// Fused normalize + TWO hole-fill iterations in one kernel (radius-2 halo).
// Invariant: stored (p, m) pairs satisfy p == tex * m (holes carry 0), so
// both iterations are the same stencil:
//   nsum = box3(p), ncnt = box3(m)
//   out_p = m ? p : (ncnt > 0 ? nsum/ncnt : 0);  out_m = m | (ncnt > 0)
// Iter-1 values outside the image are forced to 0 (reference zero-pads).
// ---------------------------------------------------------------------------
__device__ __forceinline__ float4 add3(float4 a, float4 b, float4 c) {
    return make_float4(__fadd_rn(__fadd_rn(a.x, b.x), c.x),
                       __fadd_rn(__fadd_rn(a.y, b.y), c.y),
                       __fadd_rn(__fadd_rn(a.z, b.z), c.z),
                       __fadd_rn(__fadd_rn(a.w, b.w), c.w));
}

// stencil finalize: covered -> passthrough; hole -> neighbor average (exact div)
__device__ __forceinline__ float4 fin(float4 cen, float4 ns) {
    bool covered = cen.w > 0.f;
    float nm = ns.w > 0.f ? 1.f : 0.f;
    float nd = fmaxf(ns.w, EPS);
    float4 o;
    o.x = covered ? cen.x : __fmul_rn(__fdiv_rn(ns.x, nd), nm);
    o.y = covered ? cen.y : __fmul_rn(__fdiv_rn(ns.y, nd), nm);
    o.z = covered ? cen.z : __fmul_rn(__fdiv_rn(ns.z, nd), nm);
    o.w = fmaxf(cen.w, nm);
    return o;
}

__global__ __launch_bounds__(256) void fill2x_kernel(float* __restrict__ otex) {
    __shared__ float4 sm[36 * 36];   // normalized tile+halo; later iter-1 result (34x34, stride 36)
    __shared__ float4 hs[36 * 34];   // horizontal 3-sums (iter1); later iter2 (34x32, stride 32)

    int n   = blockIdx.z;
    int tx0 = blockIdx.x << 5;
    int ty0 = blockIdx.y << 5;
    const float4* __restrict__ base = g_acc + n * PLANE;
    int t = threadIdx.x;   // 256 threads

    // ---- Load 36x36 halo, normalize: tex = acc/max(w,eps); p = tex*m; m = w>0
    for (int i = t; i < 36 * 36; i += 256) {
        int ly = i / 36, lx = i - ly * 36;
        int gx = tx0 + lx - 2, gy = ty0 + ly - 2;
        float4 v = make_float4(0.f, 0.f, 0.f, 0.f);
        if ((unsigned)gx < (unsigned)S && (unsigned)gy < (unsigned)S) {
            v = __ldg(base + gy * S + gx);
            float m = v.w > 0.f ? 1.f : 0.f;
            float d = fmaxf(v.w, EPS);
            v.x = __fmul_rn(__fdiv_rn(v.x, d), m);
            v.y = __fmul_rn(__fdiv_rn(v.y, d), m);
            v.z = __fmul_rn(__fdiv_rn(v.z, d), m);
            v.w = m;
        }
        sm[i] = v;
    }
    __syncthreads();

    // ---- Iter 1 horizontal 3-sums: 36 rows x 34 cols
    for (int i = t; i < 36 * 34; i += 256) {
        int r = i / 34, c = i - r * 34;
        const float4* row = sm + r * 36 + c;
        hs[i] = add3(row[0], row[1], row[2]);
    }
    __syncthreads();

    // ---- Iter 1 vertical + finalize into registers (34x34 outputs)
    float4 reg[5];
    int cnt = 0;
    for (int i = t; i < 34 * 34; i += 256) {
        int a = i / 34, b = i - a * 34;
        float4 ns  = add3(hs[a * 34 + b], hs[(a + 1) * 34 + b], hs[(a + 2) * 34 + b]);
        float4 cen = sm[(a + 1) * 36 + (b + 1)];
        float4 o = fin(cen, ns);
        // zero outside the image: reference pads with exact zeros
        int gy = ty0 + a - 1, gx = tx0 + b - 1;
        if ((unsigned)gx >= (unsigned)S || (unsigned)gy >= (unsigned)S)
            o = make_float4(0.f, 0.f, 0.f, 0.f);
        reg[cnt++] = o;
    }
    __syncthreads();

    // ---- Write iter-1 result back over sm (top-left 34x34, keep stride 36)
    cnt = 0;
    for (int i = t; i < 34 * 34; i += 256) {
        int a = i / 34, b = i - a * 34;
        sm[a * 36 + b] = reg[cnt++];
    }
    __syncthreads();

    // ---- Iter 2 horizontal 3-sums: 34 rows x 32 cols (reuse hs, stride 32)
    for (int i = t; i < 34 * 32; i += 256) {
        int r = i >> 5, c = i & 31;
        const float4* row = sm + r * 36 + c;
        hs[r * 32 + c] = add3(row[0], row[1], row[2]);
    }
    __syncthreads();

    // ---- Iter 2 vertical + finalize -> packed [N,S,S,3] output
    int lx = t & 31;
    for (int ly = t >> 5; ly < 32; ly += 8) {
        float4 ns  = add3(hs[ly * 32 + lx], hs[(ly + 1) * 32 + lx], hs[(ly + 2) * 32 + lx]);
        float4 cen = sm[(ly + 1) * 36 + (lx + 1)];
        float4 o = fin(cen, ns);

        int gy = ty0 + ly, gx = tx0 + lx;
        float* op = otex + ((size_t)n * PLANE + (size_t)gy * S + gx) * 3;
        op[0] = o.x; op[1] = o.y; op[2] = o.z;
    }
}

// ---------------------------------------------------------------------------
// Launch: zero -> splat -> fused normalize+fill2x (-> d_out)
// ---------------------------------------------------------------------------
extern "C" void kernel_launch(void* const* d_in, const int* in_sizes, int n_in,
                              void* d_out, int out_size) {
    const float*  img = (const float*)d_in[0];      // [4,3,1024,1024]
    const float2* uv  = (const float2*)d_in[1];     // [4,1024,1024,2]
    float* out = (float*)d_out;                     // [4,1024,1024,3]

    zero_kernel<<<TEXELS / 256, 256>>>();
    splat_kernel<<<TEXELS / 256, 256>>>(img, uv);

    dim3 grid(S / 32, S / 32, NB);
    fill2x_kernel<<<grid, 256>>>(out);
}

// round 4
// speedup vs baseline: 1.1014x; 1.0087x over previous
#include <cuda_runtime.h>

#define S 1024
#define NB 4
#define PLANE (S * S)
#define TEXELS (NB * PLANE)   // 4M texels
#define EPS 1e-8f

// Scratch: 64 MB accumulator (rgb + weight).
__device__ float4 g_acc[TEXELS];

// Vectorized L2 reduction: one 16B atomic add instead of 4 scalar atomicAdds.
__device__ __forceinline__ void red_add_v4(float4* addr, float a, float b, float c, float d) {
    asm volatile("red.global.add.v4.f32 [%0], {%1, %2, %3, %4};"
                 :: "l"(addr), "f"(a), "f"(b), "f"(c), "f"(d)
                 : "memory");
}

// ---------------------------------------------------------------------------
// Bilinear splat: one thread per source pixel, 4 corner RED.v4 ops.
// All rounding-sensitive math uses explicit _rn intrinsics so nvcc cannot
// FMA-contract (reference rounds mul and sub separately; contraction of
// v = 1023 - y*1023 flips floor() for ~hundreds of pixels -> 1e-3 error).
// ---------------------------------------------------------------------------
__global__ void splat_kernel(const float* __restrict__ img,
                             const float2* __restrict__ uv) {
    int tid = blockIdx.x * blockDim.x + threadIdx.x;   // 0 .. 4M-1
    int n  = tid >> 20;
    int hw = tid & (PLANE - 1);

    float2 t = uv[tid];
    const float* base = img + (size_t)n * 3 * PLANE + hw;
    float r = __ldg(base);
    float g = __ldg(base + PLANE);
    float b = __ldg(base + 2 * PLANE);

    float u = __fmul_rn(t.x, 1023.0f);
    float v = __fsub_rn(1023.0f, __fmul_rn(t.y, 1023.0f));
    float x0f = floorf(u), y0f = floorf(v);
    float fx = __fsub_rn(u, x0f);
    float fy = __fsub_rn(v, y0f);
    int x0 = (int)x0f, y0 = (int)y0f;
    int x1 = x0 + 1,   y1 = y0 + 1;

    float gx = __fsub_rn(1.0f, fx);
    float gy = __fsub_rn(1.0f, fy);
    float w00 = __fmul_rn(gx, gy);
    float w10 = __fmul_rn(fx, gy);
    float w01 = __fmul_rn(gx, fy);
    float w11 = __fmul_rn(fx, fy);

    float4* accn = g_acc + n * PLANE;

    #define CORNER(XI, YI, WT) do {                                         \
        int xi = (XI), yi = (YI);                                           \
        float wt = (WT);                                                    \
        bool valid = ((unsigned)xi < (unsigned)S) &&                        \
                     ((unsigned)yi < (unsigned)S);                          \
        wt = valid ? wt : 0.f;                                              \
        int xc = min(max(xi, 0), S - 1);                                    \
        int yc = min(max(yi, 0), S - 1);                                    \
        red_add_v4(accn + yc * S + xc,                                      \
                   __fmul_rn(r, wt), __fmul_rn(g, wt),                      \
                   __fmul_rn(b, wt), wt);                                   \
    } while (0)

    CORNER(x0, y0, w00);
    CORNER(x1, y0, w10);
    CORNER(x0, y1, w01);
    CORNER(x1, y1, w11);
    #undef CORNER
}

// ---------------------------------------------------------------------------
// Fused normalize + TWO hole-fill iterations in one kernel (radius-2 halo).
// Invariant: stored (p, m) pairs satisfy p == tex * m (holes carry 0), so
// both iterations are the same stencil:
//   nsum = box3(p), ncnt = box3(m)
//   out_p = m ? p : (ncnt > 0 ? nsum/ncnt : 0);  out_m = m | (ncnt > 0)
// Iter-1 values outside the image are forced to 0 (reference zero-pads).
// ---------------------------------------------------------------------------
__device__ __forceinline__ float4 add3(float4 a, float4 b, float4 c) {
    return make_float4(__fadd_rn(__fadd_rn(a.x, b.x), c.x),
                       __fadd_rn(__fadd_rn(a.y, b.y), c.y),
                       __fadd_rn(__fadd_rn(a.z, b.z), c.z),
                       __fadd_rn(__fadd_rn(a.w, b.w), c.w));
}

// stencil finalize: covered -> passthrough; hole -> neighbor average (exact div)
__device__ __forceinline__ float4 fin(float4 cen, float4 ns) {
    bool covered = cen.w > 0.f;
    float nm = ns.w > 0.f ? 1.f : 0.f;
    float nd = fmaxf(ns.w, EPS);
    float4 o;
    o.x = covered ? cen.x : __fmul_rn(__fdiv_rn(ns.x, nd), nm);
    o.y = covered ? cen.y : __fmul_rn(__fdiv_rn(ns.y, nd), nm);
    o.z = covered ? cen.z : __fmul_rn(__fdiv_rn(ns.z, nd), nm);
    o.w = fmaxf(cen.w, nm);
    return o;
}

__global__ __launch_bounds__(256) void fill2x_kernel(float* __restrict__ otex) {
    __shared__ float4 sm[36 * 36];   // normalized tile+halo; later iter-1 result (34x34, stride 36)
    __shared__ float4 hs[36 * 34];   // horizontal 3-sums (iter1); later iter2 (34x32, stride 32)

    int n   = blockIdx.z;
    int tx0 = blockIdx.x << 5;
    int ty0 = blockIdx.y << 5;
    const float4* __restrict__ base = g_acc + n * PLANE;
    int t = threadIdx.x;   // 256 threads

    // ---- Load 36x36 halo, normalize: tex = acc/max(w,eps); p = tex*m; m = w>0
    for (int i = t; i < 36 * 36; i += 256) {
        int ly = i / 36, lx = i - ly * 36;
        int gx = tx0 + lx - 2, gy = ty0 + ly - 2;
        float4 v = make_float4(0.f, 0.f, 0.f, 0.f);
        if ((unsigned)gx < (unsigned)S && (unsigned)gy < (unsigned)S) {
            v = __ldg(base + gy * S + gx);
            float m = v.w > 0.f ? 1.f : 0.f;
            float d = fmaxf(v.w, EPS);
            v.x = __fmul_rn(__fdiv_rn(v.x, d), m);
            v.y = __fmul_rn(__fdiv_rn(v.y, d), m);
            v.z = __fmul_rn(__fdiv_rn(v.z, d), m);
            v.w = m;
        }
        sm[i] = v;
    }
    __syncthreads();

    // ---- Iter 1 horizontal 3-sums: 36 rows x 34 cols
    for (int i = t; i < 36 * 34; i += 256) {
        int r = i / 34, c = i - r * 34;
        const float4* row = sm + r * 36 + c;
        hs[i] = add3(row[0], row[1], row[2]);
    }
    __syncthreads();

    // ---- Iter 1 vertical + finalize into registers (34x34 outputs)
    float4 reg[5];
    int cnt = 0;
    for (int i = t; i < 34 * 34; i += 256) {
        int a = i / 34, b = i - a * 34;
        float4 ns  = add3(hs[a * 34 + b], hs[(a + 1) * 34 + b], hs[(a + 2) * 34 + b]);
        float4 cen = sm[(a + 1) * 36 + (b + 1)];
        float4 o = fin(cen, ns);
        // zero outside the image: reference pads with exact zeros
        int gy = ty0 + a - 1, gx = tx0 + b - 1;
        if ((unsigned)gx >= (unsigned)S || (unsigned)gy >= (unsigned)S)
            o = make_float4(0.f, 0.f, 0.f, 0.f);
        reg[cnt++] = o;
    }
    __syncthreads();

    // ---- Write iter-1 result back over sm (top-left 34x34, keep stride 36)
    cnt = 0;
    for (int i = t; i < 34 * 34; i += 256) {
        int a = i / 34, b = i - a * 34;
        sm[a * 36 + b] = reg[cnt++];
    }
    __syncthreads();

    // ---- Iter 2 horizontal 3-sums: 34 rows x 32 cols (reuse hs, stride 32)
    for (int i = t; i < 34 * 32; i += 256) {
        int r = i >> 5, c = i & 31;
        const float4* row = sm + r * 36 + c;
        hs[r * 32 + c] = add3(row[0], row[1], row[2]);
    }
    __syncthreads();

    // ---- Iter 2 vertical + finalize -> packed [N,S,S,3] output
    int lx = t & 31;
    for (int ly = t >> 5; ly < 32; ly += 8) {
        float4 ns  = add3(hs[ly * 32 + lx], hs[(ly + 1) * 32 + lx], hs[(ly + 2) * 32 + lx]);
        float4 cen = sm[(ly + 1) * 36 + (lx + 1)];
        float4 o = fin(cen, ns);

        int gy = ty0 + ly, gx = tx0 + lx;
        float* op = otex + ((size_t)n * PLANE + (size_t)gy * S + gx) * 3;
        op[0] = o.x; op[1] = o.y; op[2] = o.z;
    }
}

// ---------------------------------------------------------------------------
// Launch: memset(acc) -> splat -> fused normalize+fill2x (-> d_out)
// Zeroing is a memset node (no SM launch ramp; runs at full L2 write rate).
// ---------------------------------------------------------------------------
extern "C" void kernel_launch(void* const* d_in, const int* in_sizes, int n_in,
                              void* d_out, int out_size) {
    const float*  img = (const float*)d_in[0];      // [4,3,1024,1024]
    const float2* uv  = (const float2*)d_in[1];     // [4,1024,1024,2]
    float* out = (float*)d_out;                     // [4,1024,1024,3]

    void* acc_ptr = 0;
    cudaGetSymbolAddress(&acc_ptr, g_acc);
    cudaMemsetAsync(acc_ptr, 0, (size_t)TEXELS * sizeof(float4), 0);

    splat_kernel<<<TEXELS / 256, 256>>>(img, uv);

    dim3 grid(S / 32, S / 32, NB);
    fill2x_kernel<<<grid, 256>>>(out);
}